// round 7
// baseline (speedup 1.0000x reference)
#include <cuda_runtime.h>
#include <cstdint>
#include <math.h>

// QKV attention, tf32 mma.sync, FA2-style. Q persistent in smem (A-frags
// loaded per-ks, 8 live regs), P register-resident via shuffles.
// CTA = 128 queries x full seq, 4 warps, warp tile 32x64. 3 CTAs/SM.

#define NSEQ 1024
#define TQ   128
#define TK   64
#define NTHREADS 128

// smem floats: Qs[64][128] sw @0 (32KB, persistent; epilogue alias Os)
//              Ks[64][64]  sw @8192 (16KB) | Vs[64][68] @12288 (17KB) | mask
#define OF_Q 0
#define OF_K 8192
#define OF_V 12288
#define OF_M (OF_V + 64*68)
#define SMEM_FLOATS (OF_M + 64)
#define SMEM_BYTES (SMEM_FLOATS * 4)

__device__ __forceinline__ uint32_t f2tf32(float f) {
    uint32_t r; asm("cvt.rna.tf32.f32 %0, %1;" : "=r"(r) : "f"(f)); return r;
}

#define MMA_TF32(c, a, b0, b1) \
    asm volatile("mma.sync.aligned.m16n8k8.row.col.f32.tf32.tf32.f32 " \
        "{%0,%1,%2,%3}, {%4,%5,%6,%7}, {%8,%9}, {%0,%1,%2,%3};" \
        : "+f"((c)[0]), "+f"((c)[1]), "+f"((c)[2]), "+f"((c)[3]) \
        : "r"((a)[0]), "r"((a)[1]), "r"((a)[2]), "r"((a)[3]), "r"(b0), "r"(b1))

extern __shared__ float smem[];

__global__ void __launch_bounds__(NTHREADS, 3)
attn_mma_kernel(const float* __restrict__ qkv,
                const unsigned int* __restrict__ mask,
                float* __restrict__ out)
{
    float* Qs = smem + OF_Q;
    float* Ks = smem + OF_K;
    float* Vs = smem + OF_V;
    unsigned int* mS = (unsigned int*)(smem + OF_M);

    const int tid  = threadIdx.x;
    const int lane = tid & 31;
    const int warp = tid >> 5;
    const int grp  = lane >> 2;
    const int tg   = lane & 3;
    const int r0   = 32 * warp;

    const int bh = blockIdx.y, b = bh >> 4, h = bh & 15;
    const int i0 = blockIdx.x * TQ;

    const float* qb = qkv + ((size_t)b * 3072 + h * 64) * NSEQ;
    const float* kb = qb + (size_t)1024 * NSEQ;
    const float* vb = qb + (size_t)2048 * NSEQ;

    // ---- stage Q [d][i] swizzled; scale^2 = 1/8 folded onto Q only ----
    #pragma unroll
    for (int it = 0; it < 16; it++) {
        const int idx = it * NTHREADS + tid;   // 0..2047
        const int d   = idx >> 5;
        const int i4  = (idx & 31) * 4;
        const float4 v = *(const float4*)(qb + (size_t)d * NSEQ + i0 + i4);
        uint4 w;
        w.x = f2tf32(v.x * 0.125f); w.y = f2tf32(v.y * 0.125f);
        w.z = f2tf32(v.z * 0.125f); w.w = f2tf32(v.w * 0.125f);
        *(uint4*)(Qs + d * 128 + (i4 ^ ((d & 3) << 3))) = w;
    }
    __syncthreads();

    float so[2][8][4];
    #pragma unroll
    for (int mt = 0; mt < 2; mt++)
        #pragma unroll
        for (int f = 0; f < 8; f++)
            #pragma unroll
            for (int r = 0; r < 4; r++) so[mt][f][r] = 0.f;
    float lr[2][2] = {{0.f, 0.f}, {0.f, 0.f}};

    const int src0 = (lane & 28) | (tg >> 1);   // 4*grp + tg/2
    const bool odd = tg & 1;
    const int rowA0 = (r0 + grp) ^ (tg << 3);   // mt=0 A-frag row (swizzled)
    const int rowA1 = rowA0 ^ 16;               // mt=1 (bit4 flip, XOR-safe)

    for (int t = 0; t < 16; t++) {
        const int j0 = t * TK;
        if (t) __syncthreads();   // prev GEMM2 done reading Ks/Vs

        // ---- K fill: [d][j] swizzled (raw tf32, no scale) ----
        #pragma unroll
        for (int it = 0; it < 8; it++) {
            const int idx = it * NTHREADS + tid;
            const int d   = idx >> 4;
            const int j4  = (idx & 15) * 4;
            const float4 kv = *(const float4*)(kb + (size_t)d * NSEQ + j0 + j4);
            uint4 w;
            w.x = f2tf32(kv.x); w.y = f2tf32(kv.y);
            w.z = f2tf32(kv.z); w.w = f2tf32(kv.w);
            *(uint4*)(Ks + d * 64 + (j4 ^ ((d & 3) << 3))) = w;
        }
        // ---- V fill: [dd][j] stride 68 ----
        #pragma unroll
        for (int it = 0; it < 8; it++) {
            const int idx = it * NTHREADS + tid;
            const int dd  = idx >> 4;
            const int j4  = (idx & 15) * 4;
            const float4 vv = *(const float4*)(vb + (size_t)dd * NSEQ + j0 + j4);
            uint4 w;
            w.x = f2tf32(vv.x); w.y = f2tf32(vv.y);
            w.z = f2tf32(vv.z); w.w = f2tf32(vv.w);
            *(uint4*)(Vs + dd * 68 + j4) = w;
        }
        if (tid < TK) mS[tid] = mask[b * NSEQ + j0 + tid];
        __syncthreads();

        // ---- GEMM1: S = Q K^T, warp tile 32x64; A-frags per-ks from smem ----
        float sc[2][8][4];
        #pragma unroll
        for (int mt = 0; mt < 2; mt++)
            #pragma unroll
            for (int f = 0; f < 8; f++)
                #pragma unroll
                for (int r = 0; r < 4; r++) sc[mt][f][r] = 0.f;

        #pragma unroll
        for (int ks = 0; ks < 8; ks++) {
            const int d0 = 8 * ks + tg;
            const float* q0 = Qs + d0 * 128;
            const float* q1 = q0 + 4 * 128;
            uint32_t a[2][4];
            a[0][0] = __float_as_uint(q0[rowA0]);
            a[0][1] = __float_as_uint(q0[rowA0 ^ 8]);
            a[0][2] = __float_as_uint(q1[rowA0]);
            a[0][3] = __float_as_uint(q1[rowA0 ^ 8]);
            a[1][0] = __float_as_uint(q0[rowA1]);
            a[1][1] = __float_as_uint(q0[rowA1 ^ 8]);
            a[1][2] = __float_as_uint(q1[rowA1]);
            a[1][3] = __float_as_uint(q1[rowA1 ^ 8]);
            const float* k0p = Ks + d0 * 64;
            #pragma unroll
            for (int f = 0; f < 8; f++) {
                const int col = 8 * (f ^ tg) + grp;   // == (8f+grp) ^ (tg<<3)
                const uint32_t b0 = __float_as_uint(k0p[col]);
                const uint32_t b1 = __float_as_uint(k0p[4 * 64 + col]);
                MMA_TF32(sc[0][f], a[0], b0, b1);
                MMA_TF32(sc[1][f], a[1], b0, b1);
            }
        }

        // ---- softmax (no max subtraction), P kept in sc as tf32 bits ----
        #pragma unroll
        for (int f = 0; f < 8; f++) {
            const int c0 = 8 * f + 2 * tg;
            const bool m0 = (mS[c0] != 0u), m1 = (mS[c0 + 1] != 0u);
            #pragma unroll
            for (int mt = 0; mt < 2; mt++) {
                const float p0 = m0 ? __expf(sc[mt][f][0]) : 0.f;
                const float p1 = m1 ? __expf(sc[mt][f][1]) : 0.f;
                const float p2 = m0 ? __expf(sc[mt][f][2]) : 0.f;
                const float p3 = m1 ? __expf(sc[mt][f][3]) : 0.f;
                lr[mt][0] += p0 + p1;
                lr[mt][1] += p2 + p3;
                sc[mt][f][0] = __uint_as_float(f2tf32(p0));
                sc[mt][f][1] = __uint_as_float(f2tf32(p1));
                sc[mt][f][2] = __uint_as_float(f2tf32(p2));
                sc[mt][f][3] = __uint_as_float(f2tf32(p3));
            }
        }

        // ---- GEMM2: O += P V^T; A-frags via intra-warp shuffle ----
        #pragma unroll
        for (int fp = 0; fp < 8; fp++) {
            uint32_t a[2][4];
            #pragma unroll
            for (int mt = 0; mt < 2; mt++) {
                const float r00 = __shfl_sync(0xffffffffu, sc[mt][fp][0], src0);
                const float r01 = __shfl_sync(0xffffffffu, sc[mt][fp][1], src0);
                const float r02 = __shfl_sync(0xffffffffu, sc[mt][fp][2], src0);
                const float r03 = __shfl_sync(0xffffffffu, sc[mt][fp][3], src0);
                const float r10 = __shfl_sync(0xffffffffu, sc[mt][fp][0], src0 + 2);
                const float r11 = __shfl_sync(0xffffffffu, sc[mt][fp][1], src0 + 2);
                const float r12 = __shfl_sync(0xffffffffu, sc[mt][fp][2], src0 + 2);
                const float r13 = __shfl_sync(0xffffffffu, sc[mt][fp][3], src0 + 2);
                a[mt][0] = __float_as_uint(odd ? r01 : r00);
                a[mt][1] = __float_as_uint(odd ? r03 : r02);
                a[mt][2] = __float_as_uint(odd ? r11 : r10);
                a[mt][3] = __float_as_uint(odd ? r13 : r12);
            }
            const int k0 = 8 * fp;
            #pragma unroll
            for (int f = 0; f < 8; f++) {
                const float* vp = Vs + (8 * f + grp) * 68 + k0 + tg;
                const uint32_t b0 = __float_as_uint(vp[0]);
                const uint32_t b1 = __float_as_uint(vp[4]);
                MMA_TF32(so[0][f], a[0], b0, b1);
                MMA_TF32(so[1][f], a[1], b0, b1);
            }
        }
    }

    // ---- epilogue: l reduce (rows warp-exclusive), normalize, store ----
    #pragma unroll
    for (int mt = 0; mt < 2; mt++)
        #pragma unroll
        for (int hh = 0; hh < 2; hh++) {
            lr[mt][hh] += __shfl_xor_sync(0xffffffffu, lr[mt][hh], 1);
            lr[mt][hh] += __shfl_xor_sync(0xffffffffu, lr[mt][hh], 2);
        }
    float inv[2][2];
    #pragma unroll
    for (int mt = 0; mt < 2; mt++) {
        inv[mt][0] = 1.0f / lr[mt][0];
        inv[mt][1] = 1.0f / lr[mt][1];
    }

    __syncthreads();   // all warps done reading Qs/Ks/Vs
    float* Os = smem;  // [dd][i] 64x128, swizzle i' = i ^ ((dd&6)<<2)
    #pragma unroll
    for (int f = 0; f < 8; f++) {
        const int dd = 8 * f + 2 * tg;
        const int sw = (dd & 6) << 2;
        #pragma unroll
        for (int mt = 0; mt < 2; mt++) {
            const int row = (r0 + 16 * mt + grp) ^ sw;
            Os[dd * 128 + row]             = so[mt][f][0] * inv[mt][0];
            Os[(dd + 1) * 128 + row]       = so[mt][f][1] * inv[mt][0];
            Os[dd * 128 + (row ^ 8)]       = so[mt][f][2] * inv[mt][1];
            Os[(dd + 1) * 128 + (row ^ 8)] = so[mt][f][3] * inv[mt][1];
        }
    }
    __syncthreads();

    float* ob = out + ((size_t)b * 1024 + h * 64) * NSEQ + i0;
    #pragma unroll
    for (int it = 0; it < 16; it++) {
        const int lin = it * 512 + tid * 4;
        const int dd  = lin >> 7;
        const int c   = lin & 127;
        const float4 v = *(const float4*)(Os + dd * 128 + c);
        *(float4*)(ob + (size_t)dd * NSEQ + (c ^ ((dd & 6) << 2))) = v;
    }
}

extern "C" void kernel_launch(void* const* d_in, const int* in_sizes, int n_in,
                              void* d_out, int out_size)
{
    const float* qkv = (const float*)d_in[0];
    const unsigned int* mask = (const unsigned int*)d_in[1];
    float* out = (float*)d_out;

    cudaFuncSetAttribute(attn_mma_kernel,
                         cudaFuncAttributeMaxDynamicSharedMemorySize, SMEM_BYTES);

    dim3 grid(NSEQ / TQ, 64);
    attn_mma_kernel<<<grid, NTHREADS, SMEM_BYTES>>>(qkv, mask, out);
}

// round 9
// speedup vs baseline: 1.1619x; 1.1619x over previous
#include <cuda_runtime.h>
#include <cstdint>
#include <math.h>

// QKV attention, tf32 mma.sync, FA2-style. 8 warps, warp tile 16x64,
// Q & P register-resident, double-buffered K/V smem, 1 sync/tile.
// qkv (4, 3*1024, 1024) fp32, 16 heads, d=64. CTA = 128 queries x full seq.

#define NSEQ 1024
#define TQ   128
#define TK   64
#define NTHREADS 256

// smem floats: buf[2] of (Ks[64][64] sw + Vs[64][68]) | mask[2][64]
// Qs[64][128] sw (transient) and Os[64][128] sw alias buffer region.
#define BUFSZ  (4096 + 64*68)          // 8448 floats per buffer
#define OF_B0  0
#define OF_B1  BUFSZ
#define OF_M   (2*BUFSZ)
#define SMEM_FLOATS (OF_M + 128)
#define SMEM_BYTES  (SMEM_FLOATS * 4)

__device__ __forceinline__ uint32_t f2tf32(float f) {
    uint32_t r; asm("cvt.rna.tf32.f32 %0, %1;" : "=r"(r) : "f"(f)); return r;
}

#define MMA_TF32(c, a, b0, b1) \
    asm volatile("mma.sync.aligned.m16n8k8.row.col.f32.tf32.tf32.f32 " \
        "{%0,%1,%2,%3}, {%4,%5,%6,%7}, {%8,%9}, {%0,%1,%2,%3};" \
        : "+f"((c)[0]), "+f"((c)[1]), "+f"((c)[2]), "+f"((c)[3]) \
        : "r"((a)[0]), "r"((a)[1]), "r"((a)[2]), "r"((a)[3]), "r"(b0), "r"(b1))

extern __shared__ float smem[];

__global__ void __launch_bounds__(NTHREADS, 2)
attn_mma_kernel(const float* __restrict__ qkv,
                const unsigned int* __restrict__ mask,
                float* __restrict__ out)
{
    const int tid  = threadIdx.x;
    const int lane = tid & 31;
    const int warp = tid >> 5;              // 0..7, rows 16*warp..+15
    const int grp  = lane >> 2;
    const int tg   = lane & 3;
    const int r0   = 16 * warp;

    const int bh = blockIdx.y, b = bh >> 4, h = bh & 15;
    const int i0 = blockIdx.x * TQ;

    const float* qb = qkv + ((size_t)b * 3072 + h * 64) * NSEQ;
    const float* kb = qb + (size_t)1024 * NSEQ;
    const float* vb = qb + (size_t)2048 * NSEQ;
    unsigned int* mS = (unsigned int*)(smem + OF_M);

    // ---- stage Q [d][i] swizzled (transient, aliases buffers); scale^2=1/8 ----
    float* Qs = smem;
    #pragma unroll
    for (int it = 0; it < 8; it++) {
        const int idx = it * NTHREADS + tid;   // 0..2047
        const int d   = idx >> 5;
        const int i4  = (idx & 31) * 4;
        const float4 v = *(const float4*)(qb + (size_t)d * NSEQ + i0 + i4);
        uint4 w;
        w.x = f2tf32(v.x * 0.125f); w.y = f2tf32(v.y * 0.125f);
        w.z = f2tf32(v.z * 0.125f); w.w = f2tf32(v.w * 0.125f);
        *(uint4*)(Qs + d * 128 + (i4 ^ ((d & 3) << 3))) = w;
    }
    __syncthreads();

    // ---- Q fragments -> registers (32 regs, held for whole kernel) ----
    uint32_t qf[8][4];
    {
        const int rowA = (r0 + grp) ^ (tg << 3);
        #pragma unroll
        for (int ks = 0; ks < 8; ks++) {
            const int d0 = 8 * ks + tg;
            qf[ks][0] = __float_as_uint(Qs[d0 * 128 + rowA]);
            qf[ks][1] = __float_as_uint(Qs[d0 * 128 + (rowA ^ 8)]);
            qf[ks][2] = __float_as_uint(Qs[(d0 + 4) * 128 + rowA]);
            qf[ks][3] = __float_as_uint(Qs[(d0 + 4) * 128 + (rowA ^ 8)]);
        }
    }
    __syncthreads();   // Qs dead; buffers usable

    float so[8][4];
    #pragma unroll
    for (int f = 0; f < 8; f++)
        #pragma unroll
        for (int r = 0; r < 4; r++) so[f][r] = 0.f;
    float lr[2] = {0.f, 0.f};

    const int src0 = (lane & 28) | (tg >> 1);
    const bool odd = tg & 1;

    // ---- fill helper (macro keeps regs transient) ----
    #define FILL_TILE(buf, j0) do { \
        float* Ksf = smem + ((buf) ? OF_B1 : OF_B0); \
        float* Vsf = Ksf + 4096; \
        _Pragma("unroll") \
        for (int it = 0; it < 4; it++) { \
            const int idx = it * NTHREADS + tid; \
            const int d   = idx >> 4; \
            const int j4  = (idx & 15) * 4; \
            const float4 kv = *(const float4*)(kb + (size_t)d * NSEQ + (j0) + j4); \
            uint4 w; \
            w.x = f2tf32(kv.x); w.y = f2tf32(kv.y); \
            w.z = f2tf32(kv.z); w.w = f2tf32(kv.w); \
            *(uint4*)(Ksf + d * 64 + (j4 ^ ((d & 3) << 3))) = w; \
            const float4 vv = *(const float4*)(vb + (size_t)d * NSEQ + (j0) + j4); \
            uint4 u; \
            u.x = f2tf32(vv.x); u.y = f2tf32(vv.y); \
            u.z = f2tf32(vv.z); u.w = f2tf32(vv.w); \
            *(uint4*)(Vsf + d * 68 + j4) = u; \
        } \
        if (tid < TK) mS[(buf) * 64 + tid] = mask[b * NSEQ + (j0) + tid]; \
    } while (0)

    FILL_TILE(0, 0);

    for (int t = 0; t < 16; t++) {
        const int p = t & 1;
        float* Ks = smem + (p ? OF_B1 : OF_B0);
        float* Vs = Ks + 4096;
        __syncthreads();   // fill(t) visible; all warps done with buf[p]

        // ---- GEMM1: S = Q K^T, warp tile 16x64 ----
        float sc[8][4];
        #pragma unroll
        for (int f = 0; f < 8; f++)
            #pragma unroll
            for (int r = 0; r < 4; r++) sc[f][r] = 0.f;

        #pragma unroll
        for (int ks = 0; ks < 8; ks++) {
            const float* k0p = Ks + (8 * ks + tg) * 64;
            #pragma unroll
            for (int f = 0; f < 8; f++) {
                const int col = 8 * (f ^ tg) + grp;
                const uint32_t b0 = __float_as_uint(k0p[col]);
                const uint32_t b1 = __float_as_uint(k0p[4 * 64 + col]);
                MMA_TF32(sc[f], qf[ks], b0, b1);
            }
        }

        // ---- softmax (no max subtraction), P kept in sc as tf32 bits ----
        #pragma unroll
        for (int f = 0; f < 8; f++) {
            const int c0 = 8 * f + 2 * tg;
            const bool m0 = (mS[p * 64 + c0] != 0u), m1 = (mS[p * 64 + c0 + 1] != 0u);
            const float p0 = m0 ? __expf(sc[f][0]) : 0.f;
            const float p1 = m1 ? __expf(sc[f][1]) : 0.f;
            const float p2 = m0 ? __expf(sc[f][2]) : 0.f;
            const float p3 = m1 ? __expf(sc[f][3]) : 0.f;
            lr[0] += p0 + p1;
            lr[1] += p2 + p3;
            sc[f][0] = __uint_as_float(f2tf32(p0));
            sc[f][1] = __uint_as_float(f2tf32(p1));
            sc[f][2] = __uint_as_float(f2tf32(p2));
            sc[f][3] = __uint_as_float(f2tf32(p3));
        }

        // ---- prefetch fill(t+1) into other buffer (overlaps GEMM2) ----
        if (t < 15) FILL_TILE(p ^ 1, (t + 1) * TK);

        // ---- GEMM2: O += P V^T; A-frags via intra-warp shuffle ----
        #pragma unroll
        for (int fp = 0; fp < 8; fp++) {
            uint32_t a[4];
            {
                const float r00 = __shfl_sync(0xffffffffu, sc[fp][0], src0);
                const float r01 = __shfl_sync(0xffffffffu, sc[fp][1], src0);
                const float r02 = __shfl_sync(0xffffffffu, sc[fp][2], src0);
                const float r03 = __shfl_sync(0xffffffffu, sc[fp][3], src0);
                const float r10 = __shfl_sync(0xffffffffu, sc[fp][0], src0 + 2);
                const float r11 = __shfl_sync(0xffffffffu, sc[fp][1], src0 + 2);
                const float r12 = __shfl_sync(0xffffffffu, sc[fp][2], src0 + 2);
                const float r13 = __shfl_sync(0xffffffffu, sc[fp][3], src0 + 2);
                a[0] = __float_as_uint(odd ? r01 : r00);
                a[1] = __float_as_uint(odd ? r03 : r02);
                a[2] = __float_as_uint(odd ? r11 : r10);
                a[3] = __float_as_uint(odd ? r13 : r12);
            }
            const int k0 = 8 * fp;
            #pragma unroll
            for (int f = 0; f < 8; f++) {
                const float* vp = Vs + (8 * f + grp) * 68 + k0 + tg;
                const uint32_t b0 = __float_as_uint(vp[0]);
                const uint32_t b1 = __float_as_uint(vp[4]);
                MMA_TF32(so[f], a, b0, b1);
            }
        }
    }

    // ---- epilogue ----
    lr[0] += __shfl_xor_sync(0xffffffffu, lr[0], 1);
    lr[0] += __shfl_xor_sync(0xffffffffu, lr[0], 2);
    lr[1] += __shfl_xor_sync(0xffffffffu, lr[1], 1);
    lr[1] += __shfl_xor_sync(0xffffffffu, lr[1], 2);
    const float inv0 = 1.0f / lr[0];
    const float inv1 = 1.0f / lr[1];

    __syncthreads();   // all GEMM2 done; buffer region reusable
    float* Os = smem;  // [dd][i] 64x128, swizzle i' = i ^ ((dd&6)<<2)
    #pragma unroll
    for (int f = 0; f < 8; f++) {
        const int dd = 8 * f + 2 * tg;
        const int sw = (dd & 6) << 2;
        const int row = (r0 + grp) ^ sw;
        Os[dd * 128 + row]             = so[f][0] * inv0;
        Os[(dd + 1) * 128 + row]       = so[f][1] * inv0;
        Os[dd * 128 + (row ^ 8)]       = so[f][2] * inv1;
        Os[(dd + 1) * 128 + (row ^ 8)] = so[f][3] * inv1;
    }
    __syncthreads();

    float* ob = out + ((size_t)b * 1024 + h * 64) * NSEQ + i0;
    #pragma unroll
    for (int it = 0; it < 8; it++) {
        const int lin = it * 1024 + tid * 4;
        const int dd  = lin >> 7;
        const int c   = lin & 127;
        const float4 v = *(const float4*)(Os + dd * 128 + c);
        *(float4*)(ob + (size_t)dd * NSEQ + (c ^ ((dd & 6) << 2))) = v;
    }
}

extern "C" void kernel_launch(void* const* d_in, const int* in_sizes, int n_in,
                              void* d_out, int out_size)
{
    const float* qkv = (const float*)d_in[0];
    const unsigned int* mask = (const unsigned int*)d_in[1];
    float* out = (float*)d_out;

    cudaFuncSetAttribute(attn_mma_kernel,
                         cudaFuncAttributeMaxDynamicSharedMemorySize, SMEM_BYTES);

    dim3 grid(NSEQ / TQ, 64);
    attn_mma_kernel<<<grid, NTHREADS, SMEM_BYTES>>>(qkv, mask, out);
}